// round 17
// baseline (speedup 1.0000x reference)
#include <cuda_runtime.h>
#include <cuda_fp16.h>
#include <cstdint>

// Problem constants
#define CTXD   512
#define HIDD   2048
#define NCELLS 4096      // 64*64
#define NBATCH 8
#define KNN    8
#define MTOT   (NBATCH * NCELLS)   // 32768

// Scratch (allowed: __device__ globals)
__device__ __half g_aggh[(size_t)MTOT * CTXD];  // 32 MB fp16 agg
__device__ __half g_Wh[(size_t)HIDD * CTXD];    // 2 MB  fp16 W^T

// ---------------------------------------------------------------------------
// Kernel 1: fused prep, 128 threads.
//   blocks [0,1024):        W transpose -> fp16 (32x32 tiles) -- launched first
//   blocks [1024,1024+8192): agg, 4 cells/block, 2 in flight, 32-bit addressing
// ---------------------------------------------------------------------------
#define WT_BLOCKS 1024
#define PREP_BLOCKS (WT_BLOCKS + 8192)

__global__ __launch_bounds__(128) void prep_kernel(
    const float* __restrict__ x,
    const int*   __restrict__ nn_idx,
    const float* __restrict__ sim,
    const float* __restrict__ W)
{
    const int bid = blockIdx.x;
    const int t   = threadIdx.x;

    if (bid >= WT_BLOCKS) {
        // ---- agg: 4 cells, 2 in flight, 32-bit f4 indices ----
        const int ab = bid - WT_BLOCKS;
        const int n0 = (ab & 1023) * 4;
        const int b  = ab >> 10;

        __shared__ int   s_idx[4 * KNN];
        __shared__ float s_sim[4 * KNN];
        if (t < 4 * KNN) {
            // pre-scale to f4-row offset (32-bit; max 4096*128 < 2^20)
            s_idx[t] = nn_idx[n0 * KNN + t] * (CTXD / 4);
            s_sim[t] = sim[n0 * KNN + t];
        }
        __syncthreads();

        const float4* xb = reinterpret_cast<const float4*>(x) +
                           (size_t)b * NCELLS * (CTXD / 4);
        uint2* dst = reinterpret_cast<uint2*>(g_aggh) +
                     ((size_t)b * NCELLS + n0) * (CTXD / 4) + t;

#pragma unroll
        for (int cp = 0; cp < 2; cp++) {          // cell pairs (0,1) and (2,3)
            const int c0 = cp * 2;
            float4 accA = make_float4(0.f, 0.f, 0.f, 0.f);
            float4 accB = make_float4(0.f, 0.f, 0.f, 0.f);
#pragma unroll
            for (int k = 0; k < KNN; k++) {
                const float  sA = s_sim[c0 * KNN + k];
                const float  sB = s_sim[(c0 + 1) * KNN + k];
                const float4 vA = xb[(uint32_t)(s_idx[c0 * KNN + k] + t)];
                const float4 vB = xb[(uint32_t)(s_idx[(c0 + 1) * KNN + k] + t)];
                accA.x = fmaf(sA, vA.x, accA.x); accA.y = fmaf(sA, vA.y, accA.y);
                accA.z = fmaf(sA, vA.z, accA.z); accA.w = fmaf(sA, vA.w, accA.w);
                accB.x = fmaf(sB, vB.x, accB.x); accB.y = fmaf(sB, vB.y, accB.y);
                accB.z = fmaf(sB, vB.z, accB.z); accB.w = fmaf(sB, vB.w, accB.w);
            }
            __half2 a0 = __float22half2_rn(make_float2(accA.x, accA.y));
            __half2 a1 = __float22half2_rn(make_float2(accA.z, accA.w));
            __half2 b0 = __float22half2_rn(make_float2(accB.x, accB.y));
            __half2 b1 = __float22half2_rn(make_float2(accB.z, accB.w));
            uint2 pA, pB;
            pA.x = *reinterpret_cast<uint32_t*>(&a0);
            pA.y = *reinterpret_cast<uint32_t*>(&a1);
            pB.x = *reinterpret_cast<uint32_t*>(&b0);
            pB.y = *reinterpret_cast<uint32_t*>(&b1);
            dst[(size_t)c0 * (CTXD / 4)]       = pA;
            dst[(size_t)(c0 + 1) * (CTXD / 4)] = pB;
        }
    } else {
        // ---- wtrans: Wt[n][k] = (half)W[k][n], 32x32 tile ----
        const int bx = bid & 63;             // HIDD/32
        const int by = bid >> 6;             // CTXD/32
        const int tx = t & 31;
        const int ty = t >> 5;               // 0..3

        __shared__ float tile[32][33];
#pragma unroll
        for (int i = 0; i < 8; i++)
            tile[ty + i * 4][tx] =
                W[(size_t)(by * 32 + ty + i * 4) * HIDD + bx * 32 + tx];
        __syncthreads();
#pragma unroll
        for (int i = 0; i < 8; i++)
            g_Wh[(size_t)(bx * 32 + ty + i * 4) * CTXD + by * 32 + tx] =
                __float2half(tile[tx][ty + i * 4]);
    }
}

// ---------------------------------------------------------------------------
// Kernel 2: fp16 mma.sync GEMM (R9/R16 proven, untouched). 128x128 CTA tile,
// 8 warps (warp tile 32x64), BK=64, 3-stage cp.async, ldmatrix, fp32 accum,
// 2 CTA/SM.
// ---------------------------------------------------------------------------
#define BM 128
#define BN 128
#define BK 64
#define NT (CTXD / BK)         // 8 k-chunks
#define SSTRIDE 72             // BK + 8 pad (halves)
#define TILE_H (128 * SSTRIDE)
#define STAGE_H (2 * TILE_H)
#define GEMM_SMEM (3 * STAGE_H * 2)   // 110592 bytes

__device__ __forceinline__ void cpasync16(uint32_t saddr, const void* g) {
    asm volatile("cp.async.cg.shared.global [%0], [%1], 16;\n" :: "r"(saddr), "l"(g));
}
__device__ __forceinline__ void ldsm_x4(uint32_t& r0, uint32_t& r1,
                                        uint32_t& r2, uint32_t& r3, uint32_t a) {
    asm volatile("ldmatrix.sync.aligned.m8n8.x4.shared.b16 {%0,%1,%2,%3},[%4];"
                 : "=r"(r0), "=r"(r1), "=r"(r2), "=r"(r3) : "r"(a));
}

__global__ __launch_bounds__(256, 2) void gemm_hmma(
    const __half* __restrict__ A,   // [MTOT][CTXD]
    const __half* __restrict__ B,   // [HIDD][CTXD]  (W^T)
    float*        __restrict__ C)   // [MTOT][HIDD]
{
    extern __shared__ __half sm[];

    const int tid  = threadIdx.x;
    const int lane = tid & 31;
    const int warp = tid >> 5;      // 0..7
    const int wm   = warp & 3;      // 32-row M quarter
    const int wn   = warp >> 2;     // 64-col N half
    const int g    = lane >> 2;
    const int t4   = lane & 3;

    const int m0 = blockIdx.y * BM;
    const int n0 = blockIdx.x * BN;

    float acc[2][8][4];
#pragma unroll
    for (int i = 0; i < 2; i++)
#pragma unroll
        for (int j = 0; j < 8; j++)
#pragma unroll
            for (int r = 0; r < 4; r++) acc[i][j][r] = 0.f;

    auto load_chunk = [&](int buf, int kt) {
        __half* Asb = sm + buf * STAGE_H;
        __half* Bsb = Asb + TILE_H;
        const __half* Ag = A + (size_t)m0 * CTXD + kt * BK;
        const __half* Bg = B + (size_t)n0 * CTXD + kt * BK;
#pragma unroll
        for (int i = 0; i < 4; i++) {
            int idx = i * 256 + tid;
            int row = idx >> 3;
            int c8  = (idx & 7) * 8;
            cpasync16((uint32_t)__cvta_generic_to_shared(Asb + row * SSTRIDE + c8),
                      Ag + (size_t)row * CTXD + c8);
        }
#pragma unroll
        for (int i = 0; i < 4; i++) {
            int idx = i * 256 + tid;
            int row = idx >> 3;
            int c8  = (idx & 7) * 8;
            cpasync16((uint32_t)__cvta_generic_to_shared(Bsb + row * SSTRIDE + c8),
                      Bg + (size_t)row * CTXD + c8);
        }
        asm volatile("cp.async.commit_group;\n");
    };

    load_chunk(0, 0);
    load_chunk(1, 1);

    const int a_r  = lane & 15;
    const int a_k  = (lane >> 4) * 8;
    const int b_r  = lane & 7;
    const int b_no = ((lane >> 3) >> 1) * 8;
    const int b_ko = ((lane >> 3) & 1) * 8;

    for (int kt = 0; kt < NT; ++kt) {
        if (kt + 1 < NT) asm volatile("cp.async.wait_group 1;\n");
        else             asm volatile("cp.async.wait_group 0;\n");
        __syncthreads();
        if (kt + 2 < NT) load_chunk((kt + 2) % 3, kt + 2);

        const __half* Asb = sm + (kt % 3) * STAGE_H;
        const __half* Bsb = Asb + TILE_H;

#pragma unroll
        for (int ks = 0; ks < 4; ++ks) {
            const int k0 = ks * 16;

            uint32_t af[2][4];
#pragma unroll
            for (int mi = 0; mi < 2; ++mi) {
                uint32_t a = (uint32_t)__cvta_generic_to_shared(
                    Asb + (wm * 32 + mi * 16 + a_r) * SSTRIDE + k0 + a_k);
                ldsm_x4(af[mi][0], af[mi][1], af[mi][2], af[mi][3], a);
            }
            uint32_t bf[8][2];
#pragma unroll
            for (int nj = 0; nj < 4; ++nj) {
                uint32_t a = (uint32_t)__cvta_generic_to_shared(
                    Bsb + (wn * 64 + nj * 16 + b_no + b_r) * SSTRIDE + k0 + b_ko);
                ldsm_x4(bf[2 * nj][0], bf[2 * nj][1],
                        bf[2 * nj + 1][0], bf[2 * nj + 1][1], a);
            }
#pragma unroll
            for (int mi = 0; mi < 2; ++mi)
#pragma unroll
                for (int ni = 0; ni < 8; ++ni) {
                    asm volatile(
                        "mma.sync.aligned.m16n8k16.row.col.f32.f16.f16.f32 "
                        "{%0,%1,%2,%3},{%4,%5,%6,%7},{%8,%9},{%0,%1,%2,%3};\n"
                        : "+f"(acc[mi][ni][0]), "+f"(acc[mi][ni][1]),
                          "+f"(acc[mi][ni][2]), "+f"(acc[mi][ni][3])
                        : "r"(af[mi][0]), "r"(af[mi][1]),
                          "r"(af[mi][2]), "r"(af[mi][3]),
                          "r"(bf[ni][0]), "r"(bf[ni][1]));
                }
        }
        __syncthreads();
    }

    // epilogue
#pragma unroll
    for (int mi = 0; mi < 2; ++mi) {
#pragma unroll
        for (int ni = 0; ni < 8; ++ni) {
            const int r = m0 + wm * 32 + mi * 16 + g;
            const int c = n0 + wn * 64 + ni * 8 + t4 * 2;
            float2 v0 = make_float2(acc[mi][ni][0], acc[mi][ni][1]);
            float2 v1 = make_float2(acc[mi][ni][2], acc[mi][ni][3]);
            *reinterpret_cast<float2*>(C + (size_t)r * HIDD + c)       = v0;
            *reinterpret_cast<float2*>(C + (size_t)(r + 8) * HIDD + c) = v1;
        }
    }
}

// ---------------------------------------------------------------------------
extern "C" void kernel_launch(void* const* d_in, const int* in_sizes, int n_in,
                              void* d_out, int out_size) {
    const float* x      = (const float*)d_in[0];
    const float* W      = (const float*)d_in[1];
    const int*   nn_idx = (const int*)  d_in[2];
    const float* sim    = (const float*)d_in[3];
    float*       out    = (float*)d_out;

    __half* aggh = nullptr;
    __half* wh   = nullptr;
    cudaGetSymbolAddress((void**)&aggh, g_aggh);
    cudaGetSymbolAddress((void**)&wh,   g_Wh);

    cudaFuncSetAttribute(gemm_hmma,
                         cudaFuncAttributeMaxDynamicSharedMemorySize, GEMM_SMEM);

    prep_kernel<<<PREP_BLOCKS, 128>>>(x, nn_idx, sim, W);

    dim3 g2(HIDD / BN, MTOT / BM);   // (16, 256)
    gemm_hmma<<<g2, 256, GEMM_SMEM>>>(aggh, wh, out);
}